// round 9
// baseline (speedup 1.0000x reference)
#include <cuda_runtime.h>
#include <cuda_bf16.h>
#include <cstdint>

// Embedding gather + sinusoidal positional encoding.
// out[row, c] = W[ids[row], c] + (row even ? sin : cos)(row * freq(c)),
//   freq(c) = 10000^(-2c/D)
//
// D = 1024, TOKENS = 8192. Grid = 2048 CTAs x 4 rows (best shape so far).
// L2 eviction steering:
//   gathers:  ld.global.nc.L2::cache_hint (createpolicy evict_last) — pin the
//             hot gathered-W subset in L2 across graph replays
//   stores:   __stcs (st.global.cs, evict-first) — write-once output stream
// Prologue trig: Cody-Waite reduction + MUFU __sinf/__cosf.

static constexpr int D       = 1024;
static constexpr int VEC     = 4;
static constexpr int THREADS = D / VEC;   // 256
static constexpr int R       = 4;         // rows per block (multiple of 2)

// sincos for 0 <= x <= ~8200: 3-term Cody-Waite reduction mod 2*pi, then MUFU.
__device__ __forceinline__ void fast_sincos(float x, float& s, float& c)
{
    const float INV2PI = 0.15915494309189535f;
    const float C1 = 6.28125f;
    const float C2 = 1.93530717957e-3f;
    const float C3 = 6.1232339957e-10f;
    float q = rintf(x * INV2PI);
    float a = fmaf(-q, C1, x);
    a = fmaf(-q, C2, a);
    a = fmaf(-q, C3, a);
    s = __sinf(a);
    c = __cosf(a);
}

// 128-bit gather load, non-coherent, L2 evict-last via cache-hint policy
// (direct .L2::evict_last qualifier requires 256-bit width on sm_103a).
__device__ __forceinline__ float4 ldg_evict_last(const float* p)
{
    float4 v;
    asm("{\n\t"
        ".reg .b64 pol;\n\t"
        "createpolicy.fractional.L2::evict_last.b64 pol, 1.0;\n\t"
        "ld.global.nc.L2::cache_hint.v4.f32 {%0, %1, %2, %3}, [%4], pol;\n\t"
        "}"
        : "=f"(v.x), "=f"(v.y), "=f"(v.z), "=f"(v.w)
        : "l"(p));
    return v;
}

__global__ __launch_bounds__(THREADS, 6)
void emb_pe_kernel(const int* __restrict__ ids,
                   const float* __restrict__ W,
                   float* __restrict__ out)
{
    const int row0 = blockIdx.x * R;          // multiple of 4 -> even
    const int t    = threadIdx.x;             // 0..255
    const int c0   = t * VEC;                 // starting column

    // One 16B load covers this CTA's 4 ids (aligned since row0 % 4 == 0).
    const int4 ii = *reinterpret_cast<const int4*>(ids + row0);

    const float* Wc = W + c0;

    // Front-batch all 4 gathers (independent LDG.128, MLP=4), evict-last.
    const float4 v0 = ldg_evict_last(Wc + (size_t)ii.x * D);
    const float4 v1 = ldg_evict_last(Wc + (size_t)ii.y * D);
    const float4 v2 = ldg_evict_last(Wc + (size_t)ii.z * D);
    const float4 v3 = ldg_evict_last(Wc + (size_t)ii.w * D);

    // freq(c) = 2^(kexp * c),  kexp = -2*log2(10000)/D  (overlaps load latency)
    const float kexp = -13.287712379549449f * 2.0f / (float)D;
    const float pos0 = (float)row0;

    float s[VEC], c[VEC], sd[VEC], cd[VEC];
#pragma unroll
    for (int i = 0; i < VEC; i++) {
        float freq = exp2f(kexp * (float)(c0 + i));
        fast_sincos(pos0 * freq, s[i], c[i]);   // start rotor
        fast_sincos(freq,        sd[i], cd[i]); // +1 row delta rotor
    }

    float* outp = out + (size_t)row0 * D + c0;
    float4 o;

    // row0 (even): + sin
    o.x = v0.x + s[0]; o.y = v0.y + s[1]; o.z = v0.z + s[2]; o.w = v0.w + s[3];
    __stcs(reinterpret_cast<float4*>(outp), o);

#pragma unroll
    for (int i = 0; i < VEC; i++) {           // rotate +1
        float ns = fmaf(s[i], cd[i],  c[i] * sd[i]);
        float nc = fmaf(c[i], cd[i], -s[i] * sd[i]);
        s[i] = ns; c[i] = nc;
    }

    // row0+1 (odd): + cos
    o.x = v1.x + c[0]; o.y = v1.y + c[1]; o.z = v1.z + c[2]; o.w = v1.w + c[3];
    __stcs(reinterpret_cast<float4*>(outp + D), o);

#pragma unroll
    for (int i = 0; i < VEC; i++) {           // rotate +1
        float ns = fmaf(s[i], cd[i],  c[i] * sd[i]);
        float nc = fmaf(c[i], cd[i], -s[i] * sd[i]);
        s[i] = ns; c[i] = nc;
    }

    // row0+2 (even): + sin
    o.x = v2.x + s[0]; o.y = v2.y + s[1]; o.z = v2.z + s[2]; o.w = v2.w + s[3];
    __stcs(reinterpret_cast<float4*>(outp + 2 * D), o);

#pragma unroll
    for (int i = 0; i < VEC; i++) {           // rotate +1
        float ns = fmaf(s[i], cd[i],  c[i] * sd[i]);
        float nc = fmaf(c[i], cd[i], -s[i] * sd[i]);
        s[i] = ns; c[i] = nc;
    }

    // row0+3 (odd): + cos
    o.x = v3.x + c[0]; o.y = v3.y + c[1]; o.z = v3.z + c[2]; o.w = v3.w + c[3];
    __stcs(reinterpret_cast<float4*>(outp + 3 * D), o);
}

extern "C" void kernel_launch(void* const* d_in, const int* in_sizes, int n_in,
                              void* d_out, int out_size)
{
    const int*   ids = (const int*)d_in[0];
    const float* W   = (const float*)d_in[1];
    float*       out = (float*)d_out;

    const int rows = in_sizes[0];             // 8192 tokens
    emb_pe_kernel<<<rows / R, THREADS>>>(ids, W, out);
}

// round 10
// speedup vs baseline: 1.0239x; 1.0239x over previous
#include <cuda_runtime.h>
#include <cuda_bf16.h>
#include <cstdint>

// Embedding gather + sinusoidal positional encoding.
// out[row, c] = W[ids[row], c] + (row even ? sin : cos)(row * freq(c)),
//   freq(c) = 10000^(-2c/D)
//
// D = 1024, TOKENS = 8192. Grid = 1024 CTAs x 8 rows, 256 threads.
// Gathers go through cp.async.cg (LDGSTS, 16B) into SMEM — loads don't land
// in registers, so per-SM in-flight bytes are bounded by SMEM (32KB/CTA x 5
// CTAs ~ 160KB) instead of the register file (~96KB in all prior variants).
// Each thread copies and later consumes ONLY its own 16B per row, so no
// __syncthreads is needed around the smem round-trip (cp.async.wait_group 0
// orders this thread's own copies). PE via rotor recurrence seeded by
// Cody-Waite + MUFU sincos; trig prologue overlaps the async fill.

static constexpr int D       = 1024;
static constexpr int VEC     = 4;
static constexpr int THREADS = D / VEC;   // 256
static constexpr int R       = 8;         // rows per CTA (even)
static constexpr int ROWB    = D * 4;     // row bytes = 4096

// sincos for 0 <= x <= ~8200: 3-term Cody-Waite reduction mod 2*pi, then MUFU.
__device__ __forceinline__ void fast_sincos(float x, float& s, float& c)
{
    const float INV2PI = 0.15915494309189535f;
    const float C1 = 6.28125f;
    const float C2 = 1.93530717957e-3f;
    const float C3 = 6.1232339957e-10f;
    float q = rintf(x * INV2PI);
    float a = fmaf(-q, C1, x);
    a = fmaf(-q, C2, a);
    a = fmaf(-q, C3, a);
    s = __sinf(a);
    c = __cosf(a);
}

__device__ __forceinline__ void cp_async16(uint32_t smem_dst, const void* gsrc)
{
    asm volatile("cp.async.cg.shared.global [%0], [%1], 16;"
                 :: "r"(smem_dst), "l"(gsrc));
}

__global__ __launch_bounds__(THREADS, 5)
void emb_pe_kernel(const int* __restrict__ ids,
                   const float* __restrict__ W,
                   float* __restrict__ out)
{
    __shared__ __align__(16) char smem[R * ROWB];   // 32 KB

    const int row0 = blockIdx.x * R;          // multiple of 8 -> even
    const int t    = threadIdx.x;             // 0..255
    const int c0   = t * VEC;                 // starting column

    // This CTA's 8 ids: two aligned int4 loads.
    const int4 iiA = *reinterpret_cast<const int4*>(ids + row0);
    const int4 iiB = *reinterpret_cast<const int4*>(ids + row0 + 4);
    int id[R] = { iiA.x, iiA.y, iiA.z, iiA.w, iiB.x, iiB.y, iiB.z, iiB.w };

    // Issue all 8 gather slices (16 B per thread per row) into SMEM.
    uint32_t sbase;
    asm("{ .reg .u64 tmp; cvta.to.shared.u64 tmp, %1; cvt.u32.u64 %0, tmp; }"
        : "=r"(sbase) : "l"(smem));
    const char* Wb = reinterpret_cast<const char*>(W) + (size_t)c0 * 4;
#pragma unroll
    for (int r = 0; r < R; r++)
        cp_async16(sbase + r * ROWB + t * 16, Wb + (size_t)id[r] * ROWB);
    asm volatile("cp.async.commit_group;" ::: "memory");

    // Trig prologue overlaps the async fill.
    // freq(c) = 2^(kexp * c),  kexp = -2*log2(10000)/D
    const float kexp = -13.287712379549449f * 2.0f / (float)D;
    const float pos0 = (float)row0;

    float s[VEC], c[VEC], sd[VEC], cd[VEC];
#pragma unroll
    for (int i = 0; i < VEC; i++) {
        float freq = exp2f(kexp * (float)(c0 + i));
        fast_sincos(pos0 * freq, s[i], c[i]);   // start rotor
        fast_sincos(freq,        sd[i], cd[i]); // +1 row delta rotor
    }

    // Wait for THIS thread's copies (each thread reads only its own slices).
    asm volatile("cp.async.wait_group 0;" ::: "memory");

    float* outp = out + (size_t)row0 * D + c0;

#pragma unroll
    for (int r = 0; r < R; r += 2) {
        float4 v0 = *reinterpret_cast<const float4*>(smem + r * ROWB + t * 16);
        float4 v1 = *reinterpret_cast<const float4*>(smem + (r + 1) * ROWB + t * 16);

        // even row: + sin
        float4 o;
        o.x = v0.x + s[0]; o.y = v0.y + s[1]; o.z = v0.z + s[2]; o.w = v0.w + s[3];
        *reinterpret_cast<float4*>(outp + (size_t)r * D) = o;

#pragma unroll
        for (int i = 0; i < VEC; i++) {       // rotate +1
            float ns = fmaf(s[i], cd[i],  c[i] * sd[i]);
            float nc = fmaf(c[i], cd[i], -s[i] * sd[i]);
            s[i] = ns; c[i] = nc;
        }

        // odd row: + cos
        o.x = v1.x + c[0]; o.y = v1.y + c[1]; o.z = v1.z + c[2]; o.w = v1.w + c[3];
        *reinterpret_cast<float4*>(outp + (size_t)(r + 1) * D) = o;

#pragma unroll
        for (int i = 0; i < VEC; i++) {       // rotate +1
            float ns = fmaf(s[i], cd[i],  c[i] * sd[i]);
            float nc = fmaf(c[i], cd[i], -s[i] * sd[i]);
            s[i] = ns; c[i] = nc;
        }
    }
}

extern "C" void kernel_launch(void* const* d_in, const int* in_sizes, int n_in,
                              void* d_out, int out_size)
{
    const int*   ids = (const int*)d_in[0];
    const float* W   = (const float*)d_in[1];
    float*       out = (float*)d_out;

    const int rows = in_sizes[0];             // 8192 tokens
    emb_pe_kernel<<<rows / R, THREADS>>>(ids, W, out);
}